// round 8
// baseline (speedup 1.0000x reference)
#include <cuda_runtime.h>
#include <math.h>

#define B_     16
#define CH_    22
#define T_     1001
#define F_     36
#define KT_    65
#define T1_    937            // T - KT + 1
#define T1P_   944            // padded stride
#define GC_    (F_*CH_)       // 792
#define KC_    15
#define U_     885            // E length
#define UP_    888            // padded stride
#define SLEN_  935            // S length
#define SP_    944            // S padded stride
#define Q_     43
#define NCROPS_ 501
#define OUT_   4
#define FLAT_  (F_*Q_)        // 1548
#define EPSF   1e-5f

#define KSPLIT2_ 4
#define KCHUNK2_ (GC_/KSPLIT2_)   // 198
#define GSPLIT3_ 3
#define GCHUNK3_ (F_/GSPLIT3_)    // 12

typedef unsigned long long ull;

// ---------------- scratch (device globals; no allocation) ----------------
__device__ float d_h1[(size_t)B_*GC_*T1P_ + 8192]; // temporal act [b][f*CH+ch][t] (+OOB pad for prefetch)
__device__ float d_p2[(size_t)KSPLIT2_*B_*F_*T1P_]; // k2 partials [s][b][f][t]
__device__ float d_S [(size_t)B_*F_*SP_];           // 3-mean of elu(bn(spatial)) [b][f][t]
__device__ float d_p3[(size_t)GSPLIT3_*B_*F_*UP_];  // k3 partials [gs][b][f][u]
__device__ float d_G [(size_t)B_*FLAT_];            // summed pool2 [b][f*43+q]

// ---------------- f32x2 helpers ----------------
__device__ __forceinline__ ull pack2(float a, float b) {
    ull r;
    asm("mov.b64 %0, {%1, %2};" : "=l"(r) : "f"(a), "f"(b));
    return r;
}
__device__ __forceinline__ void fma2(ull& d, ull a, ull b) {
    asm("fma.rn.f32x2 %0, %1, %2, %0;" : "+l"(d) : "l"(a), "l"(b));
}
__device__ __forceinline__ float2 unpack2(ull v) {
    float2 r;
    asm("mov.b64 {%0, %1}, %2;" : "=f"(r.x), "=f"(r.y) : "l"(v));
    return r;
}
__device__ __forceinline__ float eluf(float x) {
    return x > 0.0f ? x : (__expf(x) - 1.0f);
}
__device__ __forceinline__ void bn_fold(const float* bi, const float* g, const float* bb,
                                        const float* m, const float* v, int f,
                                        float& sc, float& sh) {
    float inv = g[f] / sqrtf(v[f] + EPSF);
    sc = inv;
    sh = (bi[f] - m[f]) * inv + bb[f];
}

// ---------------- K1: temporal conv + BN + ELU ----------------
// grid (2*3, CH, B), block 128. Thread: 4 t-slots (tid+128m) x 12 f (6 f32x2 pairs).
__global__ void __launch_bounds__(128) k1_temporal(
    const float* __restrict__ x, const float* __restrict__ w_t,
    const float* __restrict__ b_t, const float* __restrict__ g_t,
    const float* __restrict__ bb_t, const float* __restrict__ m_t,
    const float* __restrict__ v_t)
{
    __shared__ ull sx2[576];               // duplicated (v,v) pairs
    __shared__ ull sw[KT_][6];             // f-pairs (w_f, w_f+1)
    const int b   = blockIdx.z;
    const int ch  = blockIdx.y;
    const int tb  = blockIdx.x / 3;
    const int fg  = blockIdx.x % 3;
    const int f0  = fg * 12;
    const int t0  = tb * 512;
    const int tid = threadIdx.x;

    for (int i = tid; i < KT_ * 6; i += 128) {
        int k = i / 6, p = i % 6;
        sw[k][p] = pack2(w_t[(f0 + 2*p) * KT_ + k],
                         w_t[(f0 + 2*p + 1) * KT_ + k]);
    }
    const float* xp = x + ((size_t)b * CH_ + ch) * T_;
    for (int i = tid; i < 576; i += 128) {
        int tg = t0 + i;
        float v = (tg < T_) ? xp[tg] : 0.0f;
        sx2[i] = pack2(v, v);
    }
    __syncthreads();

    ull acc[4][6];
#pragma unroll
    for (int m = 0; m < 4; m++)
#pragma unroll
        for (int p = 0; p < 6; p++) acc[m][p] = 0ULL;

#pragma unroll 5
    for (int k = 0; k < KT_; k++) {
        ull x0 = sx2[tid + k];
        ull x1 = sx2[tid + 128 + k];
        ull x2 = sx2[tid + 256 + k];
        ull x3 = sx2[tid + 384 + k];
        ulonglong2 w01 = *(const ulonglong2*)&sw[k][0];
        ulonglong2 w23 = *(const ulonglong2*)&sw[k][2];
        ulonglong2 w45 = *(const ulonglong2*)&sw[k][4];
        ull wv[6] = {w01.x, w01.y, w23.x, w23.y, w45.x, w45.y};
#pragma unroll
        for (int p = 0; p < 6; p++) {
            fma2(acc[0][p], x0, wv[p]);
            fma2(acc[1][p], x1, wv[p]);
            fma2(acc[2][p], x2, wv[p]);
            fma2(acc[3][p], x3, wv[p]);
        }
    }

    // fold BN per block (cheap, removes prep kernel)
    float sc[12], sh[12];
#pragma unroll
    for (int fl = 0; fl < 12; fl++)
        bn_fold(b_t, g_t, bb_t, m_t, v_t, f0 + fl, sc[fl], sh[fl]);

#pragma unroll
    for (int m = 0; m < 4; m++) {
        int t = t0 + 128 * m + tid;
        if (t < T1_) {
#pragma unroll
            for (int p = 0; p < 6; p++) {
                float2 a = unpack2(acc[m][p]);
                int fA = f0 + 2*p, fB = fA + 1;
                d_h1[((size_t)b * GC_ + (size_t)fA * CH_ + ch) * T1P_ + t]
                    = eluf(fmaf(a.x, sc[2*p], sh[2*p]));
                d_h1[((size_t)b * GC_ + (size_t)fB * CH_ + ch) * T1P_ + t]
                    = eluf(fmaf(a.y, sc[2*p + 1], sh[2*p + 1]));
            }
        }
    }
}

// ---------------- K2: spatial conv, split-K partials ----------------
// grid (4 t-tiles x 236, 3 f-groups, B*4 splits), block 64.
// Thread: 4 consecutive t (2 packed t-pairs) x 12 f. h1 via LDG.128 with depth-4 prefetch ring.
__global__ void __launch_bounds__(64) k2_spatial(const float* __restrict__ w_s)
{
    __shared__ ull sw2[KCHUNK2_ + 2][12];  // duplicated (w,w) per f; rows 198,199 zero pad
    const int b   = blockIdx.z >> 2;
    const int s   = blockIdx.z & 3;
    const int f0  = blockIdx.y * 12;
    const int t0  = blockIdx.x * 236;
    const int tid = threadIdx.x;
    const int ks0 = s * KCHUNK2_;

    for (int i = tid; i < (KCHUNK2_ + 2) * 12; i += 64) {
        int k = i / 12, f = i % 12;
        float w = (k < KCHUNK2_) ? w_s[(size_t)(f0 + f) * GC_ + ks0 + k] : 0.0f;
        sw2[k][f] = pack2(w, w);
    }
    __syncthreads();

    const int t = t0 + tid * 4;
    const float* base = d_h1 + ((size_t)(b * GC_ + ks0)) * T1P_ + t;

    ull acc[12][2];
#pragma unroll
    for (int f = 0; f < 12; f++) { acc[f][0] = 0ULL; acc[f][1] = 0ULL; }

    ulonglong2 hbuf[4];
#pragma unroll
    for (int j = 0; j < 4; j++)
        hbuf[j] = *(const ulonglong2*)(base + (size_t)j * T1P_);

#pragma unroll 1
    for (int k0 = 0; k0 < 200; k0 += 4) {
#pragma unroll
        for (int j = 0; j < 4; j++) {
            const int k = k0 + j;
            ulonglong2 h = hbuf[j];
            hbuf[j] = *(const ulonglong2*)(base + (size_t)(k + 4) * T1P_);
#pragma unroll
            for (int pf = 0; pf < 6; pf++) {
                ulonglong2 w = *(const ulonglong2*)&sw2[k][2 * pf];
                fma2(acc[2*pf][0],     h.x, w.x);
                fma2(acc[2*pf][1],     h.y, w.x);
                fma2(acc[2*pf + 1][0], h.x, w.y);
                fma2(acc[2*pf + 1][1], h.y, w.y);
            }
        }
    }

    if (t < T1_) {
        float* pb = d_p2 + ((size_t)s * B_ * F_ + (size_t)b * F_) * T1P_;
        const bool full = (t + 3 < T1_);
#pragma unroll
        for (int f = 0; f < 12; f++) {
            float* row = pb + (size_t)(f0 + f) * T1P_;
            if (full) {
                ulonglong2 v; v.x = acc[f][0]; v.y = acc[f][1];
                *(ulonglong2*)&row[t] = v;
            } else {
                float2 a0 = unpack2(acc[f][0]);
                float2 a1 = unpack2(acc[f][1]);
                float vals[4] = {a0.x, a0.y, a1.x, a1.y};
                for (int j = 0; j < 4; j++)
                    if (t + j < T1_) row[t + j] = vals[j];
            }
        }
    }
}

// ---------------- K2e: reduce partials + BN + ELU + 3-mean -> S ----------------
// grid (F, B), block 128. Vectorized float4.
__global__ void __launch_bounds__(128) k2e_reduce(
    const float* __restrict__ b_s, const float* __restrict__ g_s,
    const float* __restrict__ bb_s, const float* __restrict__ m_s,
    const float* __restrict__ v_s)
{
    __shared__ float e[T1P_];
    const int b = blockIdx.y, f = blockIdx.x;
    const int tid = threadIdx.x;
    const size_t row = ((size_t)b * F_ + f) * T1P_;
    const size_t ps = (size_t)B_ * F_ * T1P_;
    float sc, sh;
    bn_fold(b_s, g_s, bb_s, m_s, v_s, f, sc, sh);

    for (int i = tid; i < T1P_ / 4; i += 128) {
        float4 v0 = *(const float4*)&d_p2[row + 4 * i];
        float4 v1 = *(const float4*)&d_p2[ps + row + 4 * i];
        float4 v2 = *(const float4*)&d_p2[2 * ps + row + 4 * i];
        float4 v3 = *(const float4*)&d_p2[3 * ps + row + 4 * i];
        float4 r;
        r.x = eluf(fmaf(v0.x + v1.x + v2.x + v3.x, sc, sh));
        r.y = eluf(fmaf(v0.y + v1.y + v2.y + v3.y, sc, sh));
        r.z = eluf(fmaf(v0.z + v1.z + v2.z + v3.z, sc, sh));
        r.w = eluf(fmaf(v0.w + v1.w + v2.w + v3.w, sc, sh));
        *(float4*)&e[4 * i] = r;
    }
    __syncthreads();

    float* Sp = d_S + ((size_t)b * F_ + f) * SP_;
    for (int tt = tid; tt < SLEN_; tt += 128)
        Sp[tt] = (e[tt] + e[tt + 1] + e[tt + 2]) * (1.0f / 3.0f);
}

// ---------------- K3: dilation-3 conv, split-g partials ----------------
// grid (4 u-tiles x 256, 3 f-groups, B*3 g-splits), block 128.
// Thread: 2 u-slots (tid, tid+128) x 12 f (6 pairs). S duplicated in smem.
__global__ void __launch_bounds__(128) k3_dconv(const float* __restrict__ w_c)
{
    __shared__ ull sS2[GCHUNK3_][304];              // dup (s,s); window 299 used
    __shared__ ull sw[GCHUNK3_ * KC_][6];           // f-pairs
    const int b   = blockIdx.z / 3;
    const int gs  = blockIdx.z % 3;
    const int f0  = blockIdx.y * 12;
    const int g0  = gs * GCHUNK3_;
    const int u0  = blockIdx.x * 256;
    const int tid = threadIdx.x;

    for (int i = tid; i < GCHUNK3_ * 299; i += 128) {
        int g = i / 299, kk = i % 299;
        int tt = u0 + kk;
        float v = (tt < SLEN_) ? d_S[((size_t)b * F_ + g0 + g) * SP_ + tt] : 0.0f;
        sS2[g][kk] = pack2(v, v);
    }
    for (int i = tid; i < GCHUNK3_ * KC_ * 6; i += 128) {
        int idx = i / 6, p = i % 6;
        int g = idx / KC_, j = idx % KC_;
        sw[idx][p] = pack2(w_c[((size_t)(f0 + 2*p) * F_ + g0 + g) * KC_ + j],
                           w_c[((size_t)(f0 + 2*p + 1) * F_ + g0 + g) * KC_ + j]);
    }
    __syncthreads();

    ull acc0[6], acc1[6];
#pragma unroll
    for (int p = 0; p < 6; p++) { acc0[p] = 0ULL; acc1[p] = 0ULL; }

#pragma unroll 1
    for (int g = 0; g < GCHUNK3_; g++) {
#pragma unroll
        for (int j = 0; j < KC_; j++) {
            ull s0 = sS2[g][tid + 3 * j];
            ull s1 = sS2[g][tid + 128 + 3 * j];
            ulonglong2 w01 = *(const ulonglong2*)&sw[g * KC_ + j][0];
            ulonglong2 w23 = *(const ulonglong2*)&sw[g * KC_ + j][2];
            ulonglong2 w45 = *(const ulonglong2*)&sw[g * KC_ + j][4];
            fma2(acc0[0], s0, w01.x); fma2(acc1[0], s1, w01.x);
            fma2(acc0[1], s0, w01.y); fma2(acc1[1], s1, w01.y);
            fma2(acc0[2], s0, w23.x); fma2(acc1[2], s1, w23.x);
            fma2(acc0[3], s0, w23.y); fma2(acc1[3], s1, w23.y);
            fma2(acc0[4], s0, w45.x); fma2(acc1[4], s1, w45.x);
            fma2(acc0[5], s0, w45.y); fma2(acc1[5], s1, w45.y);
        }
    }

    float* pb = d_p3 + ((size_t)gs * B_ * F_ + (size_t)b * F_) * UP_;
#pragma unroll
    for (int m = 0; m < 2; m++) {
        int u = u0 + 128 * m + tid;
        if (u < U_) {
            const ull* ac = m ? acc1 : acc0;
#pragma unroll
            for (int p = 0; p < 6; p++) {
                float2 a = unpack2(ac[p]);
                pb[(size_t)(f0 + 2*p) * UP_ + u]     = a.x;
                pb[(size_t)(f0 + 2*p + 1) * UP_ + u] = a.y;
            }
        }
    }
}

// ---------------- K4: reduce partials + BN + ELU + prefix scan + windows -> G ----------------
// grid (F, B), block 1024. Warp-shuffle 3-phase scan.
__global__ void __launch_bounds__(1024) k4_windows(
    const float* __restrict__ b_c, const float* __restrict__ g_c,
    const float* __restrict__ bb_c, const float* __restrict__ m_c,
    const float* __restrict__ v_c)
{
    __shared__ float wsum[32];
    __shared__ float ps[1025];
    const int b = blockIdx.y, f = blockIdx.x;
    const int tid = threadIdx.x;
    const int lane = tid & 31, wid = tid >> 5;
    const size_t row = ((size_t)b * F_ + f) * UP_;
    const size_t pstride = (size_t)B_ * F_ * UP_;
    float sc, sh;
    bn_fold(b_c, g_c, bb_c, m_c, v_c, f, sc, sh);

    float e = 0.0f;
    if (tid < U_) {
        float v = d_p3[row + tid] + d_p3[pstride + row + tid] + d_p3[2 * pstride + row + tid];
        e = eluf(fmaf(v, sc, sh));
    }

    float xv = e;
#pragma unroll
    for (int off = 1; off < 32; off <<= 1) {
        float y = __shfl_up_sync(0xffffffffu, xv, off);
        if (lane >= off) xv += y;
    }
    if (lane == 31) wsum[wid] = xv;
    __syncthreads();
    if (wid == 0) {
        float sv = wsum[lane];
#pragma unroll
        for (int off = 1; off < 32; off <<= 1) {
            float y = __shfl_up_sync(0xffffffffu, sv, off);
            if (lane >= off) sv += y;
        }
        wsum[lane] = sv;
    }
    __syncthreads();
    float base = (wid > 0) ? wsum[wid - 1] : 0.0f;
    ps[tid + 1] = xv + base;
    if (tid == 0) ps[0] = 0.0f;
    __syncthreads();

    if (tid < Q_) {
        int q = tid;
        float s = 0.0f;
#pragma unroll
        for (int c = 0; c <= 6; c += 3)
            s += ps[9 * q + c + 501] - ps[9 * q + c];
        d_G[(size_t)b * FLAT_ + f * Q_ + q] = s * (1.0f / 3.0f);
    }
}

// ---------------- K5: FC reduce ----------------
__global__ void __launch_bounds__(128) k5_fc(
    const float* __restrict__ w_fc, const float* __restrict__ b_fc,
    float* __restrict__ out)
{
    __shared__ float red[OUT_][128];
    const int b = blockIdx.x;
    const int tid = threadIdx.x;

    float p[OUT_];
#pragma unroll
    for (int o = 0; o < OUT_; o++) p[o] = 0.0f;

    for (int i = tid; i < FLAT_; i += 128) {
        float g = d_G[(size_t)b * FLAT_ + i];
#pragma unroll
        for (int o = 0; o < OUT_; o++)
            p[o] = fmaf(g, w_fc[(size_t)o * FLAT_ + i], p[o]);
    }
#pragma unroll
    for (int o = 0; o < OUT_; o++) red[o][tid] = p[o];
    __syncthreads();
    for (int s = 64; s > 0; s >>= 1) {
        if (tid < s) {
#pragma unroll
            for (int o = 0; o < OUT_; o++) red[o][tid] += red[o][tid + s];
        }
        __syncthreads();
    }
    if (tid < OUT_)
        out[b * OUT_ + tid] = red[tid][0] * (1.0f / NCROPS_) + b_fc[tid];
}

// ---------------- launch ----------------
extern "C" void kernel_launch(void* const* d_in, const int* in_sizes, int n_in,
                              void* d_out, int out_size)
{
    const float* x      = (const float*)d_in[0];
    const float* w_t    = (const float*)d_in[1];
    const float* b_t    = (const float*)d_in[2];
    const float* bn_t_g = (const float*)d_in[3];
    const float* bn_t_b = (const float*)d_in[4];
    const float* bn_t_m = (const float*)d_in[5];
    const float* bn_t_v = (const float*)d_in[6];
    const float* w_s    = (const float*)d_in[7];
    const float* b_s    = (const float*)d_in[8];
    const float* bn_s_g = (const float*)d_in[9];
    const float* bn_s_b = (const float*)d_in[10];
    const float* bn_s_m = (const float*)d_in[11];
    const float* bn_s_v = (const float*)d_in[12];
    const float* w_c    = (const float*)d_in[13];
    const float* b_c    = (const float*)d_in[14];
    const float* bn_c_g = (const float*)d_in[15];
    const float* bn_c_b = (const float*)d_in[16];
    const float* bn_c_m = (const float*)d_in[17];
    const float* bn_c_v = (const float*)d_in[18];
    const float* w_fc   = (const float*)d_in[19];
    const float* b_fc   = (const float*)d_in[20];
    float* out = (float*)d_out;

    dim3 g1(6, CH_, B_);                      // 2112 blocks
    k1_temporal<<<g1, 128>>>(x, w_t, b_t, bn_t_g, bn_t_b, bn_t_m, bn_t_v);

    dim3 g2(4, 3, B_ * KSPLIT2_);             // 768 blocks, 64 thr
    k2_spatial<<<g2, 64>>>(w_s);

    dim3 g2e(F_, B_);                         // 576 blocks
    k2e_reduce<<<g2e, 128>>>(b_s, bn_s_g, bn_s_b, bn_s_m, bn_s_v);

    dim3 g3(4, 3, B_ * GSPLIT3_);             // 576 blocks
    k3_dconv<<<g3, 128>>>(w_c);

    dim3 g4(F_, B_);                          // 576 blocks
    k4_windows<<<g4, 1024>>>(b_c, bn_c_g, bn_c_b, bn_c_m, bn_c_v);

    k5_fc<<<B_, 128>>>(w_fc, b_fc, out);
}